// round 1
// baseline (speedup 1.0000x reference)
#include <cuda_runtime.h>
#include <math.h>

// Problem constants
#define B_   16
#define C_   256
#define NH_  8
#define HD_  32
#define N_   1024
#define M_   256
#define HID_ 24
#define EPS_ 1e-5f

// ---------------- scratch (static __device__, no allocs) ----------------
__device__ float S_q[B_ * NH_ * N_ * HD_];    // 4M
__device__ float S_k[B_ * NH_ * M_ * HD_];    // 1M
__device__ float S_v[B_ * NH_ * M_ * HD_];    // 1M
__device__ float S_attn[B_ * NH_ * N_ * M_];  // 33.5M
__device__ float S_r[B_ * NH_ * N_ * M_];     // 33.5M
__device__ float S_hout[B_ * N_ * C_];        // 4M
__device__ float S_stats1[B_ * 3 * 2];
__device__ float S_stats2[B_ * 3 * 2];
__device__ float S_stats3[B_ * 2];

__device__ __forceinline__ float wred(float v) {
#pragma unroll
    for (int o = 16; o; o >>= 1) v += __shfl_xor_sync(0xffffffffu, v, o);
    return v;
}

// ---------------- zero stats ----------------
__global__ void k_zero() {
    int t = threadIdx.x;
    if (t < 96) S_stats1[t] = 0.f;
    if (t < 96) S_stats2[t] = 0.f;
    if (t < 32) S_stats3[t] = 0.f;
}

// ---------------- kv projection: k,v = (kv^T @ Wkv^T) ----------------
// S_k[((b*8+h)*256+m)*32+d] = sum_c kv[b,c,m] * Wkv[h*32+d, c]   (rows 0..255)
// S_v ... rows 256..511
__global__ void k_kvproj(const float* __restrict__ kv, const float* __restrict__ Wkv) {
    const int b = blockIdx.x;
    const int m0 = blockIdx.y * 16;
    __shared__ float kvs[256 * 16];
    for (int idx = threadIdx.x; idx < 256 * 16; idx += 256) {
        int c = idx >> 4, i = idx & 15;
        kvs[c * 16 + i] = kv[(b * 256 + c) * 256 + m0 + i];
    }
    __syncthreads();
    int t = threadIdx.x;
    for (int jj = 0; jj < 2; jj++) {
        int j = t + jj * 256;
        float acc[16];
#pragma unroll
        for (int i = 0; i < 16; i++) acc[i] = 0.f;
        const float* wrow = Wkv + j * 256;
        for (int c = 0; c < 256; c++) {
            float w = __ldg(wrow + c);
#pragma unroll
            for (int i = 0; i < 16; i++) acc[i] += kvs[c * 16 + i] * w;
        }
        float* dst = (j < 256) ? S_k : S_v;
        int hd = j & 255;
        int h = hd >> 5, d = hd & 31;
#pragma unroll
        for (int i = 0; i < 16; i++)
            dst[((b * 8 + h) * 256 + m0 + i) * 32 + d] = acc[i];
    }
}

// ---------------- q projection ----------------
__global__ void k_qproj(const float* __restrict__ q, const float* __restrict__ Wq) {
    const int b = blockIdx.x;
    const int n0 = blockIdx.y * 32;
    __shared__ float qs[256 * 32];
    for (int idx = threadIdx.x; idx < 8192; idx += 256) {
        int c = idx >> 5, i = idx & 31;
        qs[idx] = q[(b * 256 + c) * 1024 + n0 + i];
    }
    __syncthreads();
    int t = threadIdx.x;  // c_out
    float acc[32];
#pragma unroll
    for (int i = 0; i < 32; i++) acc[i] = 0.f;
    const float* wrow = Wq + t * 256;
    for (int c = 0; c < 256; c++) {
        float w = __ldg(wrow + c);
#pragma unroll
        for (int i = 0; i < 32; i++) acc[i] += qs[c * 32 + i] * w;
    }
    int h = t >> 5, d = t & 31;
#pragma unroll
    for (int i = 0; i < 32; i++)
        S_q[((b * 8 + h) * 1024 + n0 + i) * 32 + d] = acc[i];
}

// ---------------- attention scores + softmax ----------------
__global__ void k_attn(const float* __restrict__ rpb) {
    const int bh = blockIdx.x;
    const int n0 = blockIdx.y * 64;
    __shared__ float Ks[256 * 33];
    for (int idx = threadIdx.x; idx < 8192; idx += 256) {
        int m = idx >> 5, d = idx & 31;
        Ks[m * 33 + d] = S_k[(bh * 256 + m) * 32 + d];
    }
    __syncthreads();
    const int r = threadIdx.x >> 2;
    const int p = threadIdx.x & 3;
    const int n = n0 + r;
    float qreg[32];
#pragma unroll
    for (int d = 0; d < 32; d++) qreg[d] = S_q[(bh * 1024 + n) * 32 + d];
    const float scale = 0.17677669529663689f;  // 32^-0.5
    float sc[64];
    float mx = -1e30f;
#pragma unroll 4
    for (int mm = 0; mm < 64; mm++) {
        int m = mm * 4 + p;
        float s = 0.f;
#pragma unroll
        for (int d = 0; d < 32; d++) s += qreg[d] * Ks[m * 33 + d];
        s = s * scale + __ldg(&rpb[n * 256 + m]);
        sc[mm] = s;
        mx = fmaxf(mx, s);
    }
    mx = fmaxf(mx, __shfl_xor_sync(0xffffffffu, mx, 1));
    mx = fmaxf(mx, __shfl_xor_sync(0xffffffffu, mx, 2));
    float sum = 0.f;
#pragma unroll
    for (int mm = 0; mm < 64; mm++) {
        float e = __expf(sc[mm] - mx);
        sc[mm] = e;
        sum += e;
    }
    sum += __shfl_xor_sync(0xffffffffu, sum, 1);
    sum += __shfl_xor_sync(0xffffffffu, sum, 2);
    float inv = 1.f / sum;
    float* dst = S_attn + (size_t)(bh * 1024 + n) * 256;
#pragma unroll
    for (int mm = 0; mm < 64; mm++) dst[mm * 4 + p] = sc[mm] * inv;
}

// ---------------- GN1 statistics over x = W_exp @ attn ----------------
__global__ void k_stats1(const float* __restrict__ W_exp) {
    const int b = blockIdx.x;
    const int base = blockIdx.y * 8192;
    __shared__ float we[192];
    __shared__ float red[6];
    if (threadIdx.x < 192) we[threadIdx.x] = W_exp[threadIdx.x];
    if (threadIdx.x < 6) red[threadIdx.x] = 0.f;
    __syncthreads();
    float s0 = 0, s1 = 0, s2 = 0, q0 = 0, q1 = 0, q2 = 0;
    const float* A = S_attn + (size_t)b * 2097152;
    for (int k = 0; k < 32; k++) {
        int pix = base + k * 256 + threadIdx.x;
        float a[8];
#pragma unroll
        for (int h = 0; h < 8; h++) a[h] = A[h * 262144 + pix];
#pragma unroll
        for (int o = 0; o < 24; o++) {
            float x = 0.f;
#pragma unroll
            for (int h = 0; h < 8; h++) x += we[o * 8 + h] * a[h];
            if (o < 8)       { s0 += x; q0 += x * x; }
            else if (o < 16) { s1 += x; q1 += x * x; }
            else             { s2 += x; q2 += x * x; }
        }
    }
    s0 = wred(s0); q0 = wred(q0); s1 = wred(s1);
    q1 = wred(q1); s2 = wred(s2); q2 = wred(q2);
    if ((threadIdx.x & 31) == 0) {
        atomicAdd(&red[0], s0); atomicAdd(&red[1], q0);
        atomicAdd(&red[2], s1); atomicAdd(&red[3], q1);
        atomicAdd(&red[4], s2); atomicAdd(&red[5], q2);
    }
    __syncthreads();
    if (threadIdx.x < 6) atomicAdd(&S_stats1[b * 6 + threadIdx.x], red[threadIdx.x]);
}

// ---------------- fused DLA pass ----------------
// PASS 0: expand -> GN1 -> swish -> dw3x3 -> accumulate GN2 stats
// PASS 1: same chain -> GN2 -> swish -> 1x1 reduce -> write r + GN3 stats
template <int PASS>
__global__ void k_dla(const float* __restrict__ W_exp, const float* __restrict__ g1,
                      const float* __restrict__ b1, const float* __restrict__ W_dw,
                      const float* __restrict__ g2, const float* __restrict__ b2,
                      const float* __restrict__ W_red) {
    const int m0 = blockIdx.x * 32;
    const int n0 = blockIdx.y * 16;
    const int b = blockIdx.z;
    extern __shared__ float xact[];  // 24 * 612 floats
    __shared__ float we[192], wd[216], wrd[192];
    __shared__ float g1s[24], b1s[24], g2s[24], b2s[24];
    __shared__ float mu1[3], rs1[3], mu2[3], rs2[3];
    __shared__ float red[6];
    const int t = threadIdx.x;
    if (t < 192) we[t] = W_exp[t];
    if (t < 216) wd[t] = W_dw[t];
    if (PASS == 1 && t < 192) wrd[t] = W_red[t];
    if (t < 24) {
        g1s[t] = g1[t]; b1s[t] = b1[t];
        if (PASS == 1) { g2s[t] = g2[t]; b2s[t] = b2[t]; }
    }
    if (t < 3) {
        const float cnt = 2097152.f;  // 8*1024*256
        float s = S_stats1[b * 6 + 2 * t], qq = S_stats1[b * 6 + 2 * t + 1];
        float m = s / cnt;
        mu1[t] = m;
        rs1[t] = rsqrtf(qq / cnt - m * m + EPS_);
        if (PASS == 1) {
            s = S_stats2[b * 6 + 2 * t]; qq = S_stats2[b * 6 + 2 * t + 1];
            m = s / cnt;
            mu2[t] = m;
            rs2[t] = rsqrtf(qq / cnt - m * m + EPS_);
        }
    }
    if (t < 6) red[t] = 0.f;
    __syncthreads();

    // Phase 1: build activated expand tile (with halo) in smem
    for (int idx = t; idx < 612; idx += 256) {
        int i = idx / 34, j = idx - i * 34;
        int gi = n0 - 1 + i, gj = m0 - 1 + j;
        if ((unsigned)gi < 1024u && (unsigned)gj < 256u) {
            int pix = gi * 256 + gj;
            const float* A = S_attn + (size_t)b * 2097152 + pix;
            float a[8];
#pragma unroll
            for (int h = 0; h < 8; h++) a[h] = A[h * 262144];
#pragma unroll
            for (int o = 0; o < 24; o++) {
                float x = 0.f;
#pragma unroll
                for (int h = 0; h < 8; h++) x += we[o * 8 + h] * a[h];
                int g = o >> 3;
                x = (x - mu1[g]) * rs1[g] * g1s[o] + b1s[o];
                x = x * (1.f / (1.f + __expf(-x)));
                xact[o * 612 + idx] = x;
            }
        } else {
#pragma unroll
            for (int o = 0; o < 24; o++) xact[o * 612 + idx] = 0.f;
        }
    }
    __syncthreads();

    // Phase 2: depthwise conv + pass-specific epilogue
    float sA0 = 0, sA1 = 0, sA2 = 0, qA0 = 0, qA1 = 0, qA2 = 0;
    float s3 = 0, q3 = 0;
    for (int k = 0; k < 2; k++) {
        int pixl = t + k * 256;
        int i = pixl >> 5, j = pixl & 31;
        float r[8];
        if (PASS == 1) {
#pragma unroll
            for (int h = 0; h < 8; h++) r[h] = 0.f;
        }
#pragma unroll
        for (int o = 0; o < 24; o++) {
            const float* xb = xact + o * 612 + i * 34 + j;
            const float* w = wd + o * 9;
            float y = w[0] * xb[0] + w[1] * xb[1] + w[2] * xb[2]
                    + w[3] * xb[34] + w[4] * xb[35] + w[5] * xb[36]
                    + w[6] * xb[68] + w[7] * xb[69] + w[8] * xb[70];
            if (PASS == 0) {
                if (o < 8)       { sA0 += y; qA0 += y * y; }
                else if (o < 16) { sA1 += y; qA1 += y * y; }
                else             { sA2 += y; qA2 += y * y; }
            } else {
                int g = o >> 3;
                float z = (y - mu2[g]) * rs2[g] * g2s[o] + b2s[o];
                z = z * (1.f / (1.f + __expf(-z)));
#pragma unroll
                for (int h = 0; h < 8; h++) r[h] += wrd[h * 24 + o] * z;
            }
        }
        if (PASS == 1) {
            size_t base = (size_t)b * 2097152 + (size_t)(n0 + i) * 256 + (m0 + j);
#pragma unroll
            for (int h = 0; h < 8; h++) {
                S_r[base + (size_t)h * 262144] = r[h];
                s3 += r[h];
                q3 += r[h] * r[h];
            }
        }
    }
    if (PASS == 0) {
        sA0 = wred(sA0); qA0 = wred(qA0); sA1 = wred(sA1);
        qA1 = wred(qA1); sA2 = wred(sA2); qA2 = wred(qA2);
        if ((t & 31) == 0) {
            atomicAdd(&red[0], sA0); atomicAdd(&red[1], qA0);
            atomicAdd(&red[2], sA1); atomicAdd(&red[3], qA1);
            atomicAdd(&red[4], sA2); atomicAdd(&red[5], qA2);
        }
        __syncthreads();
        if (t < 6) atomicAdd(&S_stats2[b * 6 + t], red[t]);
    } else {
        s3 = wred(s3); q3 = wred(q3);
        if ((t & 31) == 0) {
            atomicAdd(&red[0], s3); atomicAdd(&red[1], q3);
        }
        __syncthreads();
        if (t < 2) atomicAdd(&S_stats3[b * 2 + t], red[t]);
    }
}

// ---------------- AV product (with GN3 applied on the fly) ----------------
__global__ void k_av(const float* __restrict__ g3, const float* __restrict__ b3) {
    const int bh = blockIdx.x;
    const int n0 = blockIdx.y * 32;
    const int b = bh >> 3, h = bh & 7;
    extern __shared__ float sm[];
    float* vs = sm;          // 8192
    float* rs = sm + 8192;   // 8192
    __shared__ float params[2];
    if (threadIdx.x == 0) {
        const float cnt = 2097152.f;
        float s = S_stats3[b * 2], qq = S_stats3[b * 2 + 1];
        float m = s / cnt;
        float rstd = rsqrtf(qq / cnt - m * m + EPS_);
        float gh = g3[h];
        params[0] = rstd * gh;
        params[1] = b3[h] - m * rstd * gh;
    }
    __syncthreads();
    float scl = params[0], sft = params[1];
    for (int idx = threadIdx.x; idx < 8192; idx += 256)
        vs[idx] = S_v[(size_t)bh * 8192 + idx];
    const float* R = S_r + (size_t)(bh * 1024 + n0) * 256;
    for (int idx = threadIdx.x; idx < 8192; idx += 256)
        rs[idx] = R[idx] * scl + sft;
    __syncthreads();
    int d = threadIdx.x & 31, nb = threadIdx.x >> 5;
#pragma unroll
    for (int k = 0; k < 4; k++) {
        int nl = nb + k * 8;
        float acc = 0.f;
#pragma unroll 4
        for (int m = 0; m < 256; m++) acc += rs[nl * 256 + m] * vs[m * 32 + d];
        S_hout[(size_t)(b * 1024 + n0 + nl) * 256 + h * 32 + d] = acc;
    }
}

// ---------------- output projection + NCHW transpose ----------------
__global__ void k_out(const float* __restrict__ Wp, const float* __restrict__ bp,
                      float* __restrict__ out) {
    const int b = blockIdx.x;
    const int n0 = blockIdx.y * 32;
    extern __shared__ float sm2[];
    float* hs = sm2;          // 32*257 = 8224
    float* os = sm2 + 8224;   // 256*33 = 8448
    for (int idx = threadIdx.x; idx < 8192; idx += 256) {
        int nl = idx >> 8, c = idx & 255;
        hs[nl * 257 + c] = S_hout[(size_t)(b * 1024 + n0 + nl) * 256 + c];
    }
    __syncthreads();
    int c = threadIdx.x;
    float acc[32];
#pragma unroll
    for (int i = 0; i < 32; i++) acc[i] = 0.f;
    const float* wrow = Wp + c * 256;
    for (int cp = 0; cp < 256; cp++) {
        float w = __ldg(wrow + cp);
#pragma unroll
        for (int i = 0; i < 32; i++) acc[i] += hs[i * 257 + cp] * w;
    }
    float bpc = bp[c];
#pragma unroll
    for (int i = 0; i < 32; i++) os[c * 33 + i] = acc[i] + bpc;
    __syncthreads();
    for (int idx = threadIdx.x; idx < 8192; idx += 256) {
        int c2 = idx >> 5, i2 = idx & 31;
        out[((size_t)b * 256 + c2) * 1024 + n0 + i2] = os[c2 * 33 + i2];
    }
}

// ---------------- host launcher ----------------
extern "C" void kernel_launch(void* const* d_in, const int* in_sizes, int n_in,
                              void* d_out, int out_size) {
    const float* q     = (const float*)d_in[0];
    const float* kv    = (const float*)d_in[1];
    const float* Wq    = (const float*)d_in[2];
    const float* Wkv   = (const float*)d_in[3];
    const float* Wp    = (const float*)d_in[4];
    const float* bp    = (const float*)d_in[5];
    const float* rpb   = (const float*)d_in[6];
    const float* W_exp = (const float*)d_in[7];
    const float* g1    = (const float*)d_in[8];
    const float* b1    = (const float*)d_in[9];
    const float* W_dw  = (const float*)d_in[10];
    const float* g2    = (const float*)d_in[11];
    const float* b2    = (const float*)d_in[12];
    const float* W_red = (const float*)d_in[13];
    const float* g3    = (const float*)d_in[14];
    const float* b3    = (const float*)d_in[15];
    float* out = (float*)d_out;

    cudaFuncSetAttribute(k_dla<0>, cudaFuncAttributeMaxDynamicSharedMemorySize, 24 * 612 * 4);
    cudaFuncSetAttribute(k_dla<1>, cudaFuncAttributeMaxDynamicSharedMemorySize, 24 * 612 * 4);
    cudaFuncSetAttribute(k_av, cudaFuncAttributeMaxDynamicSharedMemorySize, 65536);
    cudaFuncSetAttribute(k_out, cudaFuncAttributeMaxDynamicSharedMemorySize, 66688);

    k_zero<<<1, 128>>>();
    k_kvproj<<<dim3(16, 16), 256>>>(kv, Wkv);
    k_qproj<<<dim3(16, 32), 256>>>(q, Wq);
    k_attn<<<dim3(128, 16), 256>>>(rpb);
    k_stats1<<<dim3(16, 32), 256>>>(W_exp);
    k_dla<0><<<dim3(8, 64, 16), 256, 24 * 612 * 4>>>(W_exp, g1, b1, W_dw, g2, b2, W_red);
    k_dla<1><<<dim3(8, 64, 16), 256, 24 * 612 * 4>>>(W_exp, g1, b1, W_dw, g2, b2, W_red);
    k_av<<<dim3(128, 32), 256, 65536>>>(g3, b3);
    k_out<<<dim3(16, 32), 256, 66688>>>(Wp, bp, out);
}

// round 2
// speedup vs baseline: 1.7550x; 1.7550x over previous
#include <cuda_runtime.h>
#include <math.h>

// Problem constants
#define B_   16
#define C_   256
#define NH_  8
#define HD_  32
#define N_   1024
#define M_   256
#define HID_ 24
#define EPS_ 1e-5f

// ---------------- scratch (static __device__, no allocs) ----------------
__device__ float S_q[B_ * NH_ * N_ * HD_];        // 16 MB
__device__ float S_k[B_ * NH_ * M_ * HD_];        // 4 MB
__device__ float S_v[B_ * NH_ * M_ * HD_];        // 4 MB
__device__ float S_attn[B_ * NH_ * N_ * M_];      // 134 MB
__device__ float S_y[B_ * HID_ * N_ * M_];        // 403 MB  dwconv output
__device__ float S_r[B_ * NH_ * N_ * M_];         // 134 MB
__device__ float S_hout[B_ * N_ * C_];            // 16 MB
__device__ float S_stats1[B_ * 3 * 2];
__device__ float S_stats2[B_ * 3 * 2];
__device__ float S_stats3[B_ * 2];

__device__ __forceinline__ float wred(float v) {
#pragma unroll
    for (int o = 16; o; o >>= 1) v += __shfl_xor_sync(0xffffffffu, v, o);
    return v;
}
__device__ __forceinline__ float fsig(float x) {
    return __fdividef(1.f, 1.f + __expf(-x));
}

// ---------------- zero stats ----------------
__global__ void k_zero() {
    int t = threadIdx.x;
    if (t < 96) S_stats1[t] = 0.f;
    if (t < 96) S_stats2[t] = 0.f;
    if (t < 32) S_stats3[t] = 0.f;
}

// ---------------- kv projection ----------------
__global__ void k_kvproj(const float* __restrict__ kv, const float* __restrict__ Wkv) {
    const int b = blockIdx.x;
    const int m0 = blockIdx.y * 16;
    __shared__ float kvs[256 * 16];
    for (int idx = threadIdx.x; idx < 256 * 16; idx += 256) {
        int c = idx >> 4, i = idx & 15;
        kvs[c * 16 + i] = kv[(b * 256 + c) * 256 + m0 + i];
    }
    __syncthreads();
    int t = threadIdx.x;
    for (int jj = 0; jj < 2; jj++) {
        int j = t + jj * 256;
        float acc[16];
#pragma unroll
        for (int i = 0; i < 16; i++) acc[i] = 0.f;
        const float* wrow = Wkv + j * 256;
        for (int c = 0; c < 256; c++) {
            float w = __ldg(wrow + c);
            const float4* k4 = (const float4*)(kvs + c * 16);
#pragma unroll
            for (int i4 = 0; i4 < 4; i4++) {
                float4 kk = k4[i4];
                acc[i4 * 4 + 0] += kk.x * w;
                acc[i4 * 4 + 1] += kk.y * w;
                acc[i4 * 4 + 2] += kk.z * w;
                acc[i4 * 4 + 3] += kk.w * w;
            }
        }
        float* dst = (j < 256) ? S_k : S_v;
        int hd = j & 255;
        int h = hd >> 5, d = hd & 31;
#pragma unroll
        for (int i = 0; i < 16; i++)
            dst[((b * 8 + h) * 256 + m0 + i) * 32 + d] = acc[i];
    }
}

// ---------------- q projection ----------------
__global__ void k_qproj(const float* __restrict__ q, const float* __restrict__ Wq) {
    const int b = blockIdx.x;
    const int n0 = blockIdx.y * 32;
    __shared__ float qs[256 * 32];
    for (int idx = threadIdx.x; idx < 2048; idx += 256) {
        int c = idx >> 3, i4 = idx & 7;
        ((float4*)qs)[idx] = ((const float4*)(q + (b * 256 + c) * 1024 + n0))[i4];
    }
    __syncthreads();
    int t = threadIdx.x;  // c_out
    float acc[32];
#pragma unroll
    for (int i = 0; i < 32; i++) acc[i] = 0.f;
    const float* wrow = Wq + t * 256;
    for (int c = 0; c < 256; c++) {
        float w = __ldg(wrow + c);
        const float4* q4 = (const float4*)(qs + c * 32);
#pragma unroll
        for (int i4 = 0; i4 < 8; i4++) {
            float4 qq = q4[i4];
            acc[i4 * 4 + 0] += qq.x * w;
            acc[i4 * 4 + 1] += qq.y * w;
            acc[i4 * 4 + 2] += qq.z * w;
            acc[i4 * 4 + 3] += qq.w * w;
        }
    }
    int h = t >> 5, d = t & 31;
#pragma unroll
    for (int i = 0; i < 32; i++)
        S_q[((b * 8 + h) * 1024 + n0 + i) * 32 + d] = acc[i];
}

// ---------------- attention scores + softmax (float4 everywhere) ----------------
__global__ __launch_bounds__(256) void k_attn(const float* __restrict__ rpb) {
    const int bh = blockIdx.x;
    const int n0 = blockIdx.y * 64;
    __shared__ float Ks[256 * 36];  // padded stride 36 floats (144B, 16B-aligned)
    for (int idx = threadIdx.x; idx < 8192; idx += 256) {
        int m = idx >> 5, d = idx & 31;
        Ks[m * 36 + d] = S_k[(bh * 256 + m) * 32 + d];
    }
    __syncthreads();
    const int r = threadIdx.x >> 2;
    const int p = threadIdx.x & 3;
    const int n = n0 + r;
    float4 qreg[8];
    const float4* qp = (const float4*)(S_q + (size_t)(bh * 1024 + n) * 32);
#pragma unroll
    for (int i = 0; i < 8; i++) qreg[i] = qp[i];
    const float scale = 0.17677669529663689f;  // 32^-0.5
    float4 sc[16];
    float mx = -1e30f;
    const float* rp = rpb + n * 256;
#pragma unroll 4
    for (int mm = 0; mm < 16; mm++) {
        int m = mm * 16 + p * 4;
        float4 s;
        float* sp = (float*)&s;
#pragma unroll
        for (int jj = 0; jj < 4; jj++) {
            const float4* K4 = (const float4*)(Ks + (m + jj) * 36);
            float acc = 0.f;
#pragma unroll
            for (int i = 0; i < 8; i++) {
                float4 kk = K4[i];
                float4 qq = qreg[i];
                acc += qq.x * kk.x + qq.y * kk.y + qq.z * kk.z + qq.w * kk.w;
            }
            sp[jj] = acc;
        }
        float4 rb = *(const float4*)(rp + m);
        s.x = s.x * scale + rb.x;
        s.y = s.y * scale + rb.y;
        s.z = s.z * scale + rb.z;
        s.w = s.w * scale + rb.w;
        sc[mm] = s;
        mx = fmaxf(mx, fmaxf(fmaxf(s.x, s.y), fmaxf(s.z, s.w)));
    }
    mx = fmaxf(mx, __shfl_xor_sync(0xffffffffu, mx, 1));
    mx = fmaxf(mx, __shfl_xor_sync(0xffffffffu, mx, 2));
    float sum = 0.f;
#pragma unroll
    for (int mm = 0; mm < 16; mm++) {
        float4 s = sc[mm];
        s.x = __expf(s.x - mx);
        s.y = __expf(s.y - mx);
        s.z = __expf(s.z - mx);
        s.w = __expf(s.w - mx);
        sum += s.x + s.y + s.z + s.w;
        sc[mm] = s;
    }
    sum += __shfl_xor_sync(0xffffffffu, sum, 1);
    sum += __shfl_xor_sync(0xffffffffu, sum, 2);
    float inv = __fdividef(1.f, sum);
    float4* dst = (float4*)(S_attn + (size_t)(bh * 1024 + n) * 256);
#pragma unroll
    for (int mm = 0; mm < 16; mm++) {
        float4 s = sc[mm];
        s.x *= inv; s.y *= inv; s.z *= inv; s.w *= inv;
        dst[mm * 4 + p] = s;
    }
}

// ---------------- GN1 statistics over x = W_exp @ attn ----------------
__global__ void k_stats1(const float* __restrict__ W_exp) {
    const int b = blockIdx.x;
    const int base = blockIdx.y * 8192;
    __shared__ float we[192];
    __shared__ float red[6];
    if (threadIdx.x < 192) we[threadIdx.x] = W_exp[threadIdx.x];
    if (threadIdx.x < 6) red[threadIdx.x] = 0.f;
    __syncthreads();
    float s0 = 0, s1 = 0, s2 = 0, q0 = 0, q1 = 0, q2 = 0;
    const float* A = S_attn + (size_t)b * 2097152;
    for (int k = 0; k < 32; k++) {
        int pix = base + k * 256 + threadIdx.x;
        float a[8];
#pragma unroll
        for (int h = 0; h < 8; h++) a[h] = A[h * 262144 + pix];
#pragma unroll
        for (int o = 0; o < 24; o++) {
            float x = 0.f;
#pragma unroll
            for (int h = 0; h < 8; h++) x += we[o * 8 + h] * a[h];
            if (o < 8)       { s0 += x; q0 += x * x; }
            else if (o < 16) { s1 += x; q1 += x * x; }
            else             { s2 += x; q2 += x * x; }
        }
    }
    s0 = wred(s0); q0 = wred(q0); s1 = wred(s1);
    q1 = wred(q1); s2 = wred(s2); q2 = wred(q2);
    if ((threadIdx.x & 31) == 0) {
        atomicAdd(&red[0], s0); atomicAdd(&red[1], q0);
        atomicAdd(&red[2], s1); atomicAdd(&red[3], q1);
        atomicAdd(&red[4], s2); atomicAdd(&red[5], q2);
    }
    __syncthreads();
    if (threadIdx.x < 6) atomicAdd(&S_stats1[b * 6 + threadIdx.x], red[threadIdx.x]);
}

// ---------------- DLA pass 0: expand->GN1->swish->dw3x3 -> store y + GN2 stats ----------------
__global__ __launch_bounds__(256) void k_dla0(
    const float* __restrict__ W_exp, const float* __restrict__ g1,
    const float* __restrict__ b1, const float* __restrict__ W_dw) {
    const int m0 = blockIdx.x * 32;
    const int n0 = blockIdx.y * 16;
    const int b = blockIdx.z;
    extern __shared__ float xact[];  // 24 * 612 floats
    __shared__ float we[192], wd[216];
    __shared__ float g1s[24], b1s[24];
    __shared__ float mu1[3], rs1[3];
    __shared__ float red[6];
    const int t = threadIdx.x;
    if (t < 192) we[t] = W_exp[t];
    if (t < 216) wd[t] = W_dw[t];
    if (t < 24) { g1s[t] = g1[t]; b1s[t] = b1[t]; }
    if (t < 3) {
        const float cnt = 2097152.f;
        float s = S_stats1[b * 6 + 2 * t], qq = S_stats1[b * 6 + 2 * t + 1];
        float m = s / cnt;
        mu1[t] = m;
        rs1[t] = rsqrtf(qq / cnt - m * m + EPS_);
    }
    if (t < 6) red[t] = 0.f;
    __syncthreads();

    // Phase 1: build activated expand tile (with halo) in smem
    for (int idx = t; idx < 612; idx += 256) {
        int i = idx / 34, j = idx - i * 34;
        int gi = n0 - 1 + i, gj = m0 - 1 + j;
        if ((unsigned)gi < 1024u && (unsigned)gj < 256u) {
            int pix = gi * 256 + gj;
            const float* A = S_attn + (size_t)b * 2097152 + pix;
            float a[8];
#pragma unroll
            for (int h = 0; h < 8; h++) a[h] = A[h * 262144];
#pragma unroll
            for (int o = 0; o < 24; o++) {
                float x = 0.f;
#pragma unroll
                for (int h = 0; h < 8; h++) x += we[o * 8 + h] * a[h];
                int g = o >> 3;
                x = (x - mu1[g]) * rs1[g] * g1s[o] + b1s[o];
                x = x * fsig(x);
                xact[o * 612 + idx] = x;
            }
        } else {
#pragma unroll
            for (int o = 0; o < 24; o++) xact[o * 612 + idx] = 0.f;
        }
    }
    __syncthreads();

    // Phase 2: depthwise conv, write y coalesced, accumulate GN2 stats
    float s0 = 0, s1 = 0, s2 = 0, q0 = 0, q1 = 0, q2 = 0;
    for (int k = 0; k < 2; k++) {
        int pixl = t + k * 256;
        int i = pixl >> 5, j = pixl & 31;
        size_t gp = (size_t)(n0 + i) * 256 + (m0 + j);
#pragma unroll
        for (int o = 0; o < 24; o++) {
            const float* xb = xact + o * 612 + i * 34 + j;
            const float* w = wd + o * 9;
            float y = w[0] * xb[0] + w[1] * xb[1] + w[2] * xb[2]
                    + w[3] * xb[34] + w[4] * xb[35] + w[5] * xb[36]
                    + w[6] * xb[68] + w[7] * xb[69] + w[8] * xb[70];
            S_y[((size_t)(b * 24 + o)) * 262144 + gp] = y;
            if (o < 8)       { s0 += y; q0 += y * y; }
            else if (o < 16) { s1 += y; q1 += y * y; }
            else             { s2 += y; q2 += y * y; }
        }
    }
    s0 = wred(s0); q0 = wred(q0); s1 = wred(s1);
    q1 = wred(q1); s2 = wred(s2); q2 = wred(q2);
    if ((t & 31) == 0) {
        atomicAdd(&red[0], s0); atomicAdd(&red[1], q0);
        atomicAdd(&red[2], s1); atomicAdd(&red[3], q1);
        atomicAdd(&red[4], s2); atomicAdd(&red[5], q2);
    }
    __syncthreads();
    if (t < 6) atomicAdd(&S_stats2[b * 6 + t], red[t]);
}

// ---------------- DLA pass 1 (cheap stream): GN2->swish->1x1 reduce -> r + GN3 stats ----------------
__global__ __launch_bounds__(256) void k_red(
    const float* __restrict__ g2, const float* __restrict__ b2,
    const float* __restrict__ W_red) {
    const int b = blockIdx.x;
    const int pix0 = blockIdx.y * 2048;
    __shared__ float wrd[192], g2s[24], b2s[24];
    __shared__ float mu2[3], rs2[3];
    __shared__ float red[2];
    const int t = threadIdx.x;
    if (t < 192) wrd[t] = W_red[t];
    if (t < 24) { g2s[t] = g2[t]; b2s[t] = b2[t]; }
    if (t < 3) {
        const float cnt = 2097152.f;
        float s = S_stats2[b * 6 + 2 * t], qq = S_stats2[b * 6 + 2 * t + 1];
        float m = s / cnt;
        mu2[t] = m;
        rs2[t] = rsqrtf(qq / cnt - m * m + EPS_);
    }
    if (t < 2) red[t] = 0.f;
    __syncthreads();
    float s3 = 0, q3 = 0;
    const float* Y = S_y + (size_t)b * 24 * 262144;
    float* R = S_r + (size_t)b * 8 * 262144;
#pragma unroll 2
    for (int k = 0; k < 8; k++) {
        int pix = pix0 + k * 256 + t;
        float r[8];
#pragma unroll
        for (int h = 0; h < 8; h++) r[h] = 0.f;
#pragma unroll
        for (int o = 0; o < 24; o++) {
            float y = Y[(size_t)o * 262144 + pix];
            int g = o >> 3;
            float z = (y - mu2[g]) * rs2[g] * g2s[o] + b2s[o];
            z = z * fsig(z);
#pragma unroll
            for (int h = 0; h < 8; h++) r[h] += wrd[h * 24 + o] * z;
        }
#pragma unroll
        for (int h = 0; h < 8; h++) {
            R[(size_t)h * 262144 + pix] = r[h];
            s3 += r[h];
            q3 += r[h] * r[h];
        }
    }
    s3 = wred(s3); q3 = wred(q3);
    if ((t & 31) == 0) { atomicAdd(&red[0], s3); atomicAdd(&red[1], q3); }
    __syncthreads();
    if (t < 2) atomicAdd(&S_stats3[b * 2 + t], red[t]);
}

// ---------------- AV product (GN3 applied on the fly), 4x4 register tile ----------------
__global__ __launch_bounds__(256) void k_av(const float* __restrict__ g3, const float* __restrict__ b3) {
    const int bh = blockIdx.x;
    const int n0 = blockIdx.y * 32;
    const int b = bh >> 3, h = bh & 7;
    extern __shared__ float sm[];
    float* vs = sm;          // 8192
    float* rs = sm + 8192;   // 8192
    __shared__ float params[2];
    if (threadIdx.x == 0) {
        const float cnt = 2097152.f;
        float s = S_stats3[b * 2], qq = S_stats3[b * 2 + 1];
        float m = s / cnt;
        float rstd = rsqrtf(qq / cnt - m * m + EPS_);
        float gh = g3[h];
        params[0] = rstd * gh;
        params[1] = b3[h] - m * rstd * gh;
    }
    __syncthreads();
    float scl = params[0], sft = params[1];
    for (int idx = threadIdx.x; idx < 8192; idx += 256)
        vs[idx] = S_v[(size_t)bh * 8192 + idx];
    const float* R = S_r + (size_t)(bh * 1024 + n0) * 256;
    for (int idx = threadIdx.x; idx < 8192; idx += 256)
        rs[idx] = R[idx] * scl + sft;
    __syncthreads();
    const int d = threadIdx.x & 31, nb = threadIdx.x >> 5;
    float acc[4];
#pragma unroll
    for (int k = 0; k < 4; k++) acc[k] = 0.f;
    for (int m = 0; m < 256; m += 4) {
        float v0 = vs[m * 32 + d];
        float v1 = vs[(m + 1) * 32 + d];
        float v2 = vs[(m + 2) * 32 + d];
        float v3 = vs[(m + 3) * 32 + d];
#pragma unroll
        for (int k = 0; k < 4; k++) {
            int nl = nb + k * 8;
            float4 rr = *(const float4*)(rs + nl * 256 + m);
            acc[k] += rr.x * v0 + rr.y * v1 + rr.z * v2 + rr.w * v3;
        }
    }
#pragma unroll
    for (int k = 0; k < 4; k++) {
        int nl = nb + k * 8;
        S_hout[(size_t)(b * 1024 + n0 + nl) * 256 + h * 32 + d] = acc[k];
    }
}

// ---------------- output projection + NCHW transpose ----------------
__global__ __launch_bounds__(256) void k_out(const float* __restrict__ Wp, const float* __restrict__ bp,
                                             float* __restrict__ out) {
    const int b = blockIdx.x;
    const int n0 = blockIdx.y * 32;
    extern __shared__ float sm2[];  // 256*36 floats, reused for os (256*36)
    float* hs = sm2;
    for (int idx = threadIdx.x; idx < 8192; idx += 256) {
        int nl = idx >> 8, cp = idx & 255;
        hs[cp * 36 + nl] = S_hout[(size_t)(b * 1024 + n0 + nl) * 256 + cp];
    }
    __syncthreads();
    int c = threadIdx.x;
    float acc[32];
#pragma unroll
    for (int i = 0; i < 32; i++) acc[i] = 0.f;
    const float* wrow = Wp + c * 256;
    for (int cp = 0; cp < 256; cp++) {
        float w = __ldg(wrow + cp);
        const float4* h4 = (const float4*)(hs + cp * 36);
#pragma unroll
        for (int i4 = 0; i4 < 8; i4++) {
            float4 hh = h4[i4];
            acc[i4 * 4 + 0] += hh.x * w;
            acc[i4 * 4 + 1] += hh.y * w;
            acc[i4 * 4 + 2] += hh.z * w;
            acc[i4 * 4 + 3] += hh.w * w;
        }
    }
    float bpc = bp[c];
    __syncthreads();
    float* os = sm2;  // reuse, stride 36
#pragma unroll
    for (int i = 0; i < 32; i++) os[c * 36 + i] = acc[i] + bpc;
    __syncthreads();
    for (int idx = threadIdx.x; idx < 8192; idx += 256) {
        int c2 = idx >> 5, i2 = idx & 31;
        out[((size_t)b * 256 + c2) * 1024 + n0 + i2] = os[c2 * 36 + i2];
    }
}

// ---------------- host launcher ----------------
extern "C" void kernel_launch(void* const* d_in, const int* in_sizes, int n_in,
                              void* d_out, int out_size) {
    const float* q     = (const float*)d_in[0];
    const float* kv    = (const float*)d_in[1];
    const float* Wq    = (const float*)d_in[2];
    const float* Wkv   = (const float*)d_in[3];
    const float* Wp    = (const float*)d_in[4];
    const float* bp    = (const float*)d_in[5];
    const float* rpb   = (const float*)d_in[6];
    const float* W_exp = (const float*)d_in[7];
    const float* g1    = (const float*)d_in[8];
    const float* b1    = (const float*)d_in[9];
    const float* W_dw  = (const float*)d_in[10];
    const float* g2    = (const float*)d_in[11];
    const float* b2    = (const float*)d_in[12];
    const float* W_red = (const float*)d_in[13];
    const float* g3    = (const float*)d_in[14];
    const float* b3    = (const float*)d_in[15];
    float* out = (float*)d_out;

    cudaFuncSetAttribute(k_dla0, cudaFuncAttributeMaxDynamicSharedMemorySize, 24 * 612 * 4);
    cudaFuncSetAttribute(k_av, cudaFuncAttributeMaxDynamicSharedMemorySize, 65536);
    cudaFuncSetAttribute(k_out, cudaFuncAttributeMaxDynamicSharedMemorySize, 256 * 36 * 4);

    k_zero<<<1, 128>>>();
    k_kvproj<<<dim3(16, 16), 256>>>(kv, Wkv);
    k_qproj<<<dim3(16, 32), 256>>>(q, Wq);
    k_attn<<<dim3(128, 16), 256>>>(rpb);
    k_stats1<<<dim3(16, 32), 256>>>(W_exp);
    k_dla0<<<dim3(8, 64, 16), 256, 24 * 612 * 4>>>(W_exp, g1, b1, W_dw);
    k_red<<<dim3(16, 128), 256>>>(g2, b2, W_red);
    k_av<<<dim3(128, 32), 256, 65536>>>(g3, b3);
    k_out<<<dim3(16, 32), 256, 256 * 36 * 4>>>(Wp, bp, out);
}